// round 1
// baseline (speedup 1.0000x reference)
#include <cuda_runtime.h>

// Problem constants
#define Bb   2
#define Ss   2048
#define Hh   1024
#define NHh  16
#define HDd  64
#define Mrows (Bb*Ss)   // 4096

// ---------------------------------------------------------------------------
// Device scratch (no allocations allowed)
// ---------------------------------------------------------------------------
__device__ float g_q[Bb*NHh*Ss*HDd];    // [b,h,s,d]
__device__ float g_k[Bb*NHh*Ss*HDd];
__device__ float g_v[Bb*NHh*Ss*HDd];
__device__ float g_ctx[Bb*Ss*Hh];       // [b,s,h]

// ---------------------------------------------------------------------------
// GEMM: Y[M,N] = X[M,K] @ W[N,K]^T + bias, M=4096, N=K=1024
// dst: 0 -> Yout (plain [m][n])
//      1/2/3 -> g_q/g_k/g_v with head-major remap [b,h,s,d]
// src: 0 -> Xin arg, 1 -> g_ctx
// 64x64 block tile, KT=16, 256 threads, 4x4 microtile per thread.
// ---------------------------------------------------------------------------
__global__ __launch_bounds__(256)
void gemm64(const float* __restrict__ Xin,
            const float* __restrict__ W,
            const float* __restrict__ bias,
            float* __restrict__ Yout,
            int src, int dst)
{
    const float* X = (src == 1) ? g_ctx : Xin;

    __shared__ float Xs[16][68];
    __shared__ float Ws[16][68];

    const int tid = threadIdx.x;
    const int tx  = tid & 15;       // col group
    const int ty  = tid >> 4;       // row group
    const int m0  = blockIdx.y * 64;
    const int n0  = blockIdx.x * 64;

    const int lr = tid >> 2;        // 0..63: tile row being loaded
    const int lc = (tid & 3) << 2;  // k offset within 16

    float acc[4][4];
#pragma unroll
    for (int i = 0; i < 4; i++)
#pragma unroll
        for (int j = 0; j < 4; j++) acc[i][j] = 0.f;

    const float* xg = X + (size_t)(m0 + lr) * Hh + lc;
    const float* wg = W + (size_t)(n0 + lr) * Hh + lc;

    for (int k0 = 0; k0 < Hh; k0 += 16) {
        float4 xv = *(const float4*)(xg + k0);
        float4 wv = *(const float4*)(wg + k0);
        Xs[lc+0][lr] = xv.x; Xs[lc+1][lr] = xv.y;
        Xs[lc+2][lr] = xv.z; Xs[lc+3][lr] = xv.w;
        Ws[lc+0][lr] = wv.x; Ws[lc+1][lr] = wv.y;
        Ws[lc+2][lr] = wv.z; Ws[lc+3][lr] = wv.w;
        __syncthreads();

#pragma unroll
        for (int k = 0; k < 16; k++) {
            float4 a  = *(const float4*)&Xs[k][ty << 2];
            float4 b4 = *(const float4*)&Ws[k][tx << 2];
            float av[4] = {a.x, a.y, a.z, a.w};
            float bv[4] = {b4.x, b4.y, b4.z, b4.w};
#pragma unroll
            for (int i = 0; i < 4; i++)
#pragma unroll
                for (int j = 0; j < 4; j++)
                    acc[i][j] += av[i] * bv[j];
        }
        __syncthreads();
    }

#pragma unroll
    for (int i = 0; i < 4; i++) {
        const int m = m0 + (ty << 2) + i;
#pragma unroll
        for (int j = 0; j < 4; j++) {
            const int n = n0 + (tx << 2) + j;
            float v = acc[i][j] + bias[n];
            if (dst == 0) {
                Yout[(size_t)m * Hh + n] = v;
            } else {
                const int bb   = m / Ss;
                const int s    = m - bb * Ss;
                const int head = n >> 6;
                const int d    = n & 63;
                float* dp = (dst == 1) ? g_q : (dst == 2) ? g_k : g_v;
                dp[(((size_t)(bb * NHh + head)) * Ss + s) * HDd + d] = v;
            }
        }
    }
}

// ---------------------------------------------------------------------------
// Flash-style causal attention, fp32.
// grid: (S/64, B*NH). block: 256.
// 64 query rows per CTA, 32-wide K/V tiles, online softmax.
// Thread roles:
//   score phase: (sy=tid>>4, sx=tid&15) -> 4x2 microtile of 64x32 scores
//   softmax/PV : (q=tid>>2, jj=tid&3)   -> row q, dims jj*16..jj*16+15
// ---------------------------------------------------------------------------
__global__ __launch_bounds__(256)
void attn64()
{
    __shared__ float Qs[64][68];
    __shared__ float Ks[32][68];
    __shared__ float Vs[32][68];
    __shared__ float Ps[64][36];

    const int tid = threadIdx.x;
    const int qb  = blockIdx.x;
    const int bh  = blockIdx.y;
    const int q0  = qb * 64;

    const float* Qg = g_q + (size_t)bh * Ss * HDd;
    const float* Kg = g_k + (size_t)bh * Ss * HDd;
    const float* Vg = g_v + (size_t)bh * Ss * HDd;

    // load Q tile (64 x 64 floats = 1024 float4 units)
    for (int u = tid; u < 64 * 16; u += 256) {
        const int r = u >> 4;
        const int c = (u & 15) << 2;
        *(float4*)&Qs[r][c] = *(const float4*)&Qg[(size_t)(q0 + r) * 64 + c];
    }

    const int q  = tid >> 2;    // 0..63
    const int jj = tid & 3;     // 0..3

    float o[16];
#pragma unroll
    for (int i = 0; i < 16; i++) o[i] = 0.f;
    float mrow = -1e30f, lrow = 0.f;

    const int sx = tid & 15;
    const int sy = tid >> 4;

    const int kbmax = 2 * qb + 1;
    for (int kb = 0; kb <= kbmax; kb++) {
        const int k0 = kb * 32;
        __syncthreads();   // protect Qs (1st iter) / Ks,Vs,Ps reuse

        for (int u = tid; u < 32 * 16; u += 256) {
            const int r = u >> 4;
            const int c = (u & 15) << 2;
            *(float4*)&Ks[r][c] = *(const float4*)&Kg[(size_t)(k0 + r) * 64 + c];
            *(float4*)&Vs[r][c] = *(const float4*)&Vg[(size_t)(k0 + r) * 64 + c];
        }
        __syncthreads();

        // --- scores: S = Q K^T * scale, masked ---
        float sacc[4][2];
#pragma unroll
        for (int i = 0; i < 4; i++) { sacc[i][0] = 0.f; sacc[i][1] = 0.f; }

#pragma unroll
        for (int kk = 0; kk < 64; kk += 4) {
            float4 b0 = *(const float4*)&Ks[sx * 2 + 0][kk];
            float4 b1 = *(const float4*)&Ks[sx * 2 + 1][kk];
#pragma unroll
            for (int i = 0; i < 4; i++) {
                float4 a = *(const float4*)&Qs[sy * 4 + i][kk];
                sacc[i][0] += a.x * b0.x + a.y * b0.y + a.z * b0.z + a.w * b0.w;
                sacc[i][1] += a.x * b1.x + a.y * b1.y + a.z * b1.z + a.w * b1.w;
            }
        }
#pragma unroll
        for (int i = 0; i < 4; i++) {
            const int r = sy * 4 + i;
#pragma unroll
            for (int j = 0; j < 2; j++) {
                const int c = sx * 2 + j;
                float s = sacc[i][j] * 0.125f;           // 1/sqrt(64)
                if (k0 + c > q0 + r) s = -1e30f;          // causal mask
                Ps[r][c] = s;
            }
        }
        __syncthreads();

        // --- online softmax for row q (quad of 4 threads) ---
        float pv[8];
        float bm = -1e30f;
#pragma unroll
        for (int c = 0; c < 8; c++) {
            pv[c] = Ps[q][jj * 8 + c];
            bm = fmaxf(bm, pv[c]);
        }
        bm = fmaxf(bm, __shfl_xor_sync(0xffffffffu, bm, 1));
        bm = fmaxf(bm, __shfl_xor_sync(0xffffffffu, bm, 2));
        const float newm = fmaxf(mrow, bm);
        const float corr = __expf(mrow - newm);
        float rsum = 0.f;
#pragma unroll
        for (int c = 0; c < 8; c++) {
            float p = __expf(pv[c] - newm);
            Ps[q][jj * 8 + c] = p;
            rsum += p;
        }
        rsum += __shfl_xor_sync(0xffffffffu, rsum, 1);
        rsum += __shfl_xor_sync(0xffffffffu, rsum, 2);
        lrow = lrow * corr + rsum;
        mrow = newm;
#pragma unroll
        for (int i = 0; i < 16; i++) o[i] *= corr;
        __syncwarp();   // Ps row q probs visible within quad

        // --- O += P @ V ---
#pragma unroll
        for (int k = 0; k < 32; k++) {
            const float p = Ps[q][k];
            const float4* vr = (const float4*)&Vs[k][jj * 16];
            float4 v0 = vr[0], v1 = vr[1], v2 = vr[2], v3 = vr[3];
            o[0]  += p * v0.x;  o[1]  += p * v0.y;  o[2]  += p * v0.z;  o[3]  += p * v0.w;
            o[4]  += p * v1.x;  o[5]  += p * v1.y;  o[6]  += p * v1.z;  o[7]  += p * v1.w;
            o[8]  += p * v2.x;  o[9]  += p * v2.y;  o[10] += p * v2.z;  o[11] += p * v2.w;
            o[12] += p * v3.x;  o[13] += p * v3.y;  o[14] += p * v3.z;  o[15] += p * v3.w;
        }
    }

    // writeback: ctx[b, s, head*64 + d]
    const float inv = 1.f / lrow;
    const int b    = bh / NHh;
    const int head = bh - b * NHh;
    float* outp = &g_ctx[((size_t)(b * Ss) + q0 + q) * Hh + head * 64 + jj * 16];
#pragma unroll
    for (int i = 0; i < 4; i++) {
        float4 w;
        w.x = o[i*4+0] * inv; w.y = o[i*4+1] * inv;
        w.z = o[i*4+2] * inv; w.w = o[i*4+3] * inv;
        ((float4*)outp)[i] = w;
    }
}

// ---------------------------------------------------------------------------
// kernel_launch
// inputs: 0 hidden_states, 1 Wq, 2 bq, 3 Wk, 4 bk, 5 Wv, 6 bv, 7 Wo, 8 bo
// ---------------------------------------------------------------------------
extern "C" void kernel_launch(void* const* d_in, const int* in_sizes, int n_in,
                              void* d_out, int out_size)
{
    const float* x  = (const float*)d_in[0];
    const float* Wq = (const float*)d_in[1];
    const float* bq = (const float*)d_in[2];
    const float* Wk = (const float*)d_in[3];
    const float* bk = (const float*)d_in[4];
    const float* Wv = (const float*)d_in[5];
    const float* bv = (const float*)d_in[6];
    const float* Wo = (const float*)d_in[7];
    const float* bo = (const float*)d_in[8];
    float* out = (float*)d_out;

    dim3 ggrid(Hh / 64, Mrows / 64);   // (16, 64)
    gemm64<<<ggrid, 256>>>(x, Wq, bq, nullptr, 0, 1);
    gemm64<<<ggrid, 256>>>(x, Wk, bk, nullptr, 0, 2);
    gemm64<<<ggrid, 256>>>(x, Wv, bv, nullptr, 0, 3);

    dim3 agrid(Ss / 64, Bb * NHh);     // (32, 32)
    attn64<<<agrid, 256>>>();

    gemm64<<<ggrid, 256>>>(x, Wo, bo, out, 1, 0);
}

// round 2
// speedup vs baseline: 1.3095x; 1.3095x over previous
#include <cuda_runtime.h>
#include <cstdint>

// Problem constants
#define Bb   2
#define Ss   2048
#define Hh   1024
#define NHh  16
#define HDd  64
#define Mrows (Bb*Ss)   // 4096

// ---------------------------------------------------------------------------
// Device scratch (no allocations allowed)
// ---------------------------------------------------------------------------
__device__ float g_q[Bb*NHh*Ss*HDd];    // [b,h,s,d]
__device__ float g_k[Bb*NHh*Ss*HDd];
__device__ float g_v[Bb*NHh*Ss*HDd];
__device__ float g_ctx[Bb*Ss*Hh];       // [b,s,h]

__device__ __forceinline__ uint32_t f2tf32(float x) {
    uint32_t r;
    asm("cvt.rna.tf32.f32 %0, %1;" : "=r"(r) : "f"(x));
    return r;
}

__device__ __forceinline__ void mma_tf32(float d[4], const uint32_t a[4],
                                         const uint32_t b[2], const float c[4]) {
    asm volatile(
        "mma.sync.aligned.m16n8k8.row.col.f32.tf32.tf32.f32 "
        "{%0,%1,%2,%3}, {%4,%5,%6,%7}, {%8,%9}, {%10,%11,%12,%13};\n"
        : "=f"(d[0]), "=f"(d[1]), "=f"(d[2]), "=f"(d[3])
        : "r"(a[0]), "r"(a[1]), "r"(a[2]), "r"(a[3]),
          "r"(b[0]), "r"(b[1]),
          "f"(c[0]), "f"(c[1]), "f"(c[2]), "f"(c[3]));
}

// ---------------------------------------------------------------------------
// tf32 tensor-core GEMM: Y[M,N] = X[M,K] @ W[N,K]^T + bias
// M=4096, N=K=1024. CTA tile 128x128, BK=32, 256 threads (8 warps: 2m x 4n,
// each warp 64x32 via 4x4 grid of m16n8k8 MMAs). Register-staged double buffer.
// dst: 0 -> Yout [m][n];  1/2/3 -> g_q/g_k/g_v with [b,h,s,d] remap
// src: 0 -> Xin arg, 1 -> g_ctx
// ---------------------------------------------------------------------------
__global__ __launch_bounds__(256)
void gemm_tf32(const float* __restrict__ Xin,
               const float* __restrict__ W,
               const float* __restrict__ bias,
               float* __restrict__ Yout,
               int src, int dst)
{
    const float* X = (src == 1) ? g_ctx : Xin;

    __shared__ uint32_t A_s[128][36];
    __shared__ uint32_t B_s[128][36];

    const int tid  = threadIdx.x;
    const int lane = tid & 31;
    const int wid  = tid >> 5;
    const int wm   = (wid & 1) * 64;    // warp m offset within CTA tile
    const int wn   = (wid >> 1) * 32;   // warp n offset
    const int m0   = blockIdx.y * 128;
    const int n0   = blockIdx.x * 128;

    const int g  = lane >> 2;   // group id 0..7
    const int tg = lane & 3;    // thread-in-group

    // loader mapping: 2 threads per row, 16 floats each
    const int lrow = tid >> 1;
    const int lcol = (tid & 1) << 4;
    const float* ag = X + (size_t)(m0 + lrow) * Hh + lcol;
    const float* bg = W + (size_t)(n0 + lrow) * Hh + lcol;

    float acc[4][4][4];
#pragma unroll
    for (int mt = 0; mt < 4; mt++)
#pragma unroll
        for (int nt = 0; nt < 4; nt++)
#pragma unroll
            for (int r = 0; r < 4; r++) acc[mt][nt][r] = 0.f;

    float4 ra[4], rb[4];
#pragma unroll
    for (int j = 0; j < 4; j++) {
        ra[j] = *(const float4*)(ag + j * 4);
        rb[j] = *(const float4*)(bg + j * 4);
    }

    for (int k0 = 0; k0 < Hh; k0 += 32) {
        // stage registers -> SMEM (converted to tf32)
#pragma unroll
        for (int j = 0; j < 4; j++) {
            uint4 ua, ub;
            ua.x = f2tf32(ra[j].x); ua.y = f2tf32(ra[j].y);
            ua.z = f2tf32(ra[j].z); ua.w = f2tf32(ra[j].w);
            ub.x = f2tf32(rb[j].x); ub.y = f2tf32(rb[j].y);
            ub.z = f2tf32(rb[j].z); ub.w = f2tf32(rb[j].w);
            *(uint4*)&A_s[lrow][lcol + j * 4] = ua;
            *(uint4*)&B_s[lrow][lcol + j * 4] = ub;
        }
        __syncthreads();

        // prefetch next k tile
        if (k0 + 32 < Hh) {
            const float* agn = ag + k0 + 32;
            const float* bgn = bg + k0 + 32;
#pragma unroll
            for (int j = 0; j < 4; j++) {
                ra[j] = *(const float4*)(agn + j * 4);
                rb[j] = *(const float4*)(bgn + j * 4);
            }
        }

        // compute: 4 k-chunks of 8
#pragma unroll
        for (int kc = 0; kc < 32; kc += 8) {
            uint32_t af[4][4];
            uint32_t bf[4][2];
#pragma unroll
            for (int mt = 0; mt < 4; mt++) {
                const int r = wm + mt * 16 + g;
                af[mt][0] = A_s[r][kc + tg];
                af[mt][1] = A_s[r + 8][kc + tg];
                af[mt][2] = A_s[r][kc + tg + 4];
                af[mt][3] = A_s[r + 8][kc + tg + 4];
            }
#pragma unroll
            for (int nt = 0; nt < 4; nt++) {
                const int cN = wn + nt * 8 + g;
                bf[nt][0] = B_s[cN][kc + tg];
                bf[nt][1] = B_s[cN][kc + tg + 4];
            }
#pragma unroll
            for (int mt = 0; mt < 4; mt++)
#pragma unroll
                for (int nt = 0; nt < 4; nt++)
                    mma_tf32(acc[mt][nt], af[mt], bf[nt], acc[mt][nt]);
        }
        __syncthreads();
    }

    // epilogue: d0,d1 -> (row, col..col+1); d2,d3 -> (row+8, col..col+1)
#pragma unroll
    for (int mt = 0; mt < 4; mt++) {
#pragma unroll
        for (int nt = 0; nt < 4; nt++) {
            const int mA = m0 + wm + mt * 16 + g;
            const int nA = n0 + wn + nt * 8 + tg * 2;
            const float b0 = bias[nA], b1 = bias[nA + 1];
#pragma unroll
            for (int half = 0; half < 2; half++) {
                const int m = mA + half * 8;
                float2 v;
                v.x = acc[mt][nt][half * 2 + 0] + b0;
                v.y = acc[mt][nt][half * 2 + 1] + b1;
                if (dst == 0) {
                    *(float2*)&Yout[(size_t)m * Hh + nA] = v;
                } else {
                    const int bb   = m / Ss;
                    const int s    = m - bb * Ss;
                    const int head = nA >> 6;
                    const int d    = nA & 63;
                    float* dp = (dst == 1) ? g_q : (dst == 2) ? g_k : g_v;
                    *(float2*)&dp[(((size_t)(bb * NHh + head)) * Ss + s) * HDd + d] = v;
                }
            }
        }
    }
}

// ---------------------------------------------------------------------------
// Flash-style causal attention, fp32 (unchanged from round 1).
// grid: (S/64, B*NH). block: 256.
// ---------------------------------------------------------------------------
__global__ __launch_bounds__(256)
void attn64()
{
    __shared__ float Qs[64][68];
    __shared__ float Ks[32][68];
    __shared__ float Vs[32][68];
    __shared__ float Ps[64][36];

    const int tid = threadIdx.x;
    const int qb  = blockIdx.x;
    const int bh  = blockIdx.y;
    const int q0  = qb * 64;

    const float* Qg = g_q + (size_t)bh * Ss * HDd;
    const float* Kg = g_k + (size_t)bh * Ss * HDd;
    const float* Vg = g_v + (size_t)bh * Ss * HDd;

    for (int u = tid; u < 64 * 16; u += 256) {
        const int r = u >> 4;
        const int c = (u & 15) << 2;
        *(float4*)&Qs[r][c] = *(const float4*)&Qg[(size_t)(q0 + r) * 64 + c];
    }

    const int q  = tid >> 2;
    const int jj = tid & 3;

    float o[16];
#pragma unroll
    for (int i = 0; i < 16; i++) o[i] = 0.f;
    float mrow = -1e30f, lrow = 0.f;

    const int sx = tid & 15;
    const int sy = tid >> 4;

    const int kbmax = 2 * qb + 1;
    for (int kb = 0; kb <= kbmax; kb++) {
        const int k0 = kb * 32;
        __syncthreads();

        for (int u = tid; u < 32 * 16; u += 256) {
            const int r = u >> 4;
            const int c = (u & 15) << 2;
            *(float4*)&Ks[r][c] = *(const float4*)&Kg[(size_t)(k0 + r) * 64 + c];
            *(float4*)&Vs[r][c] = *(const float4*)&Vg[(size_t)(k0 + r) * 64 + c];
        }
        __syncthreads();

        float sacc[4][2];
#pragma unroll
        for (int i = 0; i < 4; i++) { sacc[i][0] = 0.f; sacc[i][1] = 0.f; }

#pragma unroll
        for (int kk = 0; kk < 64; kk += 4) {
            float4 b0 = *(const float4*)&Ks[sx * 2 + 0][kk];
            float4 b1 = *(const float4*)&Ks[sx * 2 + 1][kk];
#pragma unroll
            for (int i = 0; i < 4; i++) {
                float4 a = *(const float4*)&Qs[sy * 4 + i][kk];
                sacc[i][0] += a.x * b0.x + a.y * b0.y + a.z * b0.z + a.w * b0.w;
                sacc[i][1] += a.x * b1.x + a.y * b1.y + a.z * b1.z + a.w * b1.w;
            }
        }
#pragma unroll
        for (int i = 0; i < 4; i++) {
            const int r = sy * 4 + i;
#pragma unroll
            for (int j = 0; j < 2; j++) {
                const int c = sx * 2 + j;
                float s = sacc[i][j] * 0.125f;
                if (k0 + c > q0 + r) s = -1e30f;
                Ps[r][c] = s;
            }
        }
        __syncthreads();

        float pv[8];
        float bm = -1e30f;
#pragma unroll
        for (int c = 0; c < 8; c++) {
            pv[c] = Ps[q][jj * 8 + c];
            bm = fmaxf(bm, pv[c]);
        }
        bm = fmaxf(bm, __shfl_xor_sync(0xffffffffu, bm, 1));
        bm = fmaxf(bm, __shfl_xor_sync(0xffffffffu, bm, 2));
        const float newm = fmaxf(mrow, bm);
        const float corr = __expf(mrow - newm);
        float rsum = 0.f;
#pragma unroll
        for (int c = 0; c < 8; c++) {
            float p = __expf(pv[c] - newm);
            Ps[q][jj * 8 + c] = p;
            rsum += p;
        }
        rsum += __shfl_xor_sync(0xffffffffu, rsum, 1);
        rsum += __shfl_xor_sync(0xffffffffu, rsum, 2);
        lrow = lrow * corr + rsum;
        mrow = newm;
#pragma unroll
        for (int i = 0; i < 16; i++) o[i] *= corr;
        __syncwarp();

#pragma unroll
        for (int k = 0; k < 32; k++) {
            const float p = Ps[q][k];
            const float4* vr = (const float4*)&Vs[k][jj * 16];
            float4 v0 = vr[0], v1 = vr[1], v2 = vr[2], v3 = vr[3];
            o[0]  += p * v0.x;  o[1]  += p * v0.y;  o[2]  += p * v0.z;  o[3]  += p * v0.w;
            o[4]  += p * v1.x;  o[5]  += p * v1.y;  o[6]  += p * v1.z;  o[7]  += p * v1.w;
            o[8]  += p * v2.x;  o[9]  += p * v2.y;  o[10] += p * v2.z;  o[11] += p * v2.w;
            o[12] += p * v3.x;  o[13] += p * v3.y;  o[14] += p * v3.z;  o[15] += p * v3.w;
        }
    }

    const float inv = 1.f / lrow;
    const int b    = bh / NHh;
    const int head = bh - b * NHh;
    float* outp = &g_ctx[((size_t)(b * Ss) + q0 + q) * Hh + head * 64 + jj * 16];
#pragma unroll
    for (int i = 0; i < 4; i++) {
        float4 w;
        w.x = o[i*4+0] * inv; w.y = o[i*4+1] * inv;
        w.z = o[i*4+2] * inv; w.w = o[i*4+3] * inv;
        ((float4*)outp)[i] = w;
    }
}

// ---------------------------------------------------------------------------
// kernel_launch
// inputs: 0 hidden_states, 1 Wq, 2 bq, 3 Wk, 4 bk, 5 Wv, 6 bv, 7 Wo, 8 bo
// ---------------------------------------------------------------------------
extern "C" void kernel_launch(void* const* d_in, const int* in_sizes, int n_in,
                              void* d_out, int out_size)
{
    const float* x  = (const float*)d_in[0];
    const float* Wq = (const float*)d_in[1];
    const float* bq = (const float*)d_in[2];
    const float* Wk = (const float*)d_in[3];
    const float* bk = (const float*)d_in[4];
    const float* Wv = (const float*)d_in[5];
    const float* bv = (const float*)d_in[6];
    const float* Wo = (const float*)d_in[7];
    const float* bo = (const float*)d_in[8];
    float* out = (float*)d_out;

    dim3 ggrid(Hh / 128, Mrows / 128);   // (8, 32)
    gemm_tf32<<<ggrid, 256>>>(x, Wq, bq, nullptr, 0, 1);
    gemm_tf32<<<ggrid, 256>>>(x, Wk, bk, nullptr, 0, 2);
    gemm_tf32<<<ggrid, 256>>>(x, Wv, bv, nullptr, 0, 3);

    dim3 agrid(Ss / 64, Bb * NHh);       // (32, 32)
    attn64<<<agrid, 256>>>();

    gemm_tf32<<<ggrid, 256>>>(x, Wo, bo, out, 1, 0);
}

// round 3
// speedup vs baseline: 4.4890x; 3.4279x over previous
#include <cuda_runtime.h>
#include <cstdint>

// Problem constants
#define Bb   2
#define Ss   2048
#define Hh   1024
#define NHh  16
#define HDd  64
#define Mrows (Bb*Ss)   // 4096

// ---------------------------------------------------------------------------
// Device scratch (no allocations allowed)
// ---------------------------------------------------------------------------
__device__ float g_q[Bb*NHh*Ss*HDd];    // [b,h,s,d]
__device__ float g_k[Bb*NHh*Ss*HDd];
__device__ float g_v[Bb*NHh*Ss*HDd];
__device__ float g_ctx[Bb*Ss*Hh];       // [b,s,h]

__device__ __forceinline__ uint32_t f2tf32(float x) {
    uint32_t r;
    asm("cvt.rna.tf32.f32 %0, %1;" : "=r"(r) : "f"(x));
    return r;
}

__device__ __forceinline__ void mma_tf32(float d[4], const uint32_t a[4],
                                         const uint32_t b[2], const float c[4]) {
    asm volatile(
        "mma.sync.aligned.m16n8k8.row.col.f32.tf32.tf32.f32 "
        "{%0,%1,%2,%3}, {%4,%5,%6,%7}, {%8,%9}, {%10,%11,%12,%13};\n"
        : "=f"(d[0]), "=f"(d[1]), "=f"(d[2]), "=f"(d[3])
        : "r"(a[0]), "r"(a[1]), "r"(a[2]), "r"(a[3]),
          "r"(b[0]), "r"(b[1]),
          "f"(c[0]), "f"(c[1]), "f"(c[2]), "f"(c[3]));
}

// ---------------------------------------------------------------------------
// tf32 tensor-core GEMM (unchanged from round 2)
// ---------------------------------------------------------------------------
__global__ __launch_bounds__(256)
void gemm_tf32(const float* __restrict__ Xin,
               const float* __restrict__ W,
               const float* __restrict__ bias,
               float* __restrict__ Yout,
               int src, int dst)
{
    const float* X = (src == 1) ? g_ctx : Xin;

    __shared__ uint32_t A_s[128][36];
    __shared__ uint32_t B_s[128][36];

    const int tid  = threadIdx.x;
    const int lane = tid & 31;
    const int wid  = tid >> 5;
    const int wm   = (wid & 1) * 64;
    const int wn   = (wid >> 1) * 32;
    const int m0   = blockIdx.y * 128;
    const int n0   = blockIdx.x * 128;

    const int g  = lane >> 2;
    const int tg = lane & 3;

    const int lrow = tid >> 1;
    const int lcol = (tid & 1) << 4;
    const float* ag = X + (size_t)(m0 + lrow) * Hh + lcol;
    const float* bg = W + (size_t)(n0 + lrow) * Hh + lcol;

    float acc[4][4][4];
#pragma unroll
    for (int mt = 0; mt < 4; mt++)
#pragma unroll
        for (int nt = 0; nt < 4; nt++)
#pragma unroll
            for (int r = 0; r < 4; r++) acc[mt][nt][r] = 0.f;

    float4 ra[4], rb[4];
#pragma unroll
    for (int j = 0; j < 4; j++) {
        ra[j] = *(const float4*)(ag + j * 4);
        rb[j] = *(const float4*)(bg + j * 4);
    }

    for (int k0 = 0; k0 < Hh; k0 += 32) {
#pragma unroll
        for (int j = 0; j < 4; j++) {
            uint4 ua, ub;
            ua.x = f2tf32(ra[j].x); ua.y = f2tf32(ra[j].y);
            ua.z = f2tf32(ra[j].z); ua.w = f2tf32(ra[j].w);
            ub.x = f2tf32(rb[j].x); ub.y = f2tf32(rb[j].y);
            ub.z = f2tf32(rb[j].z); ub.w = f2tf32(rb[j].w);
            *(uint4*)&A_s[lrow][lcol + j * 4] = ua;
            *(uint4*)&B_s[lrow][lcol + j * 4] = ub;
        }
        __syncthreads();

        if (k0 + 32 < Hh) {
            const float* agn = ag + k0 + 32;
            const float* bgn = bg + k0 + 32;
#pragma unroll
            for (int j = 0; j < 4; j++) {
                ra[j] = *(const float4*)(agn + j * 4);
                rb[j] = *(const float4*)(bgn + j * 4);
            }
        }

#pragma unroll
        for (int kc = 0; kc < 32; kc += 8) {
            uint32_t af[4][4];
            uint32_t bf[4][2];
#pragma unroll
            for (int mt = 0; mt < 4; mt++) {
                const int r = wm + mt * 16 + g;
                af[mt][0] = A_s[r][kc + tg];
                af[mt][1] = A_s[r + 8][kc + tg];
                af[mt][2] = A_s[r][kc + tg + 4];
                af[mt][3] = A_s[r + 8][kc + tg + 4];
            }
#pragma unroll
            for (int nt = 0; nt < 4; nt++) {
                const int cN = wn + nt * 8 + g;
                bf[nt][0] = B_s[cN][kc + tg];
                bf[nt][1] = B_s[cN][kc + tg + 4];
            }
#pragma unroll
            for (int mt = 0; mt < 4; mt++)
#pragma unroll
                for (int nt = 0; nt < 4; nt++)
                    mma_tf32(acc[mt][nt], af[mt], bf[nt], acc[mt][nt]);
        }
        __syncthreads();
    }

#pragma unroll
    for (int mt = 0; mt < 4; mt++) {
#pragma unroll
        for (int nt = 0; nt < 4; nt++) {
            const int mA = m0 + wm + mt * 16 + g;
            const int nA = n0 + wn + nt * 8 + tg * 2;
            const float b0 = bias[nA], b1 = bias[nA + 1];
#pragma unroll
            for (int half = 0; half < 2; half++) {
                const int m = mA + half * 8;
                float2 v;
                v.x = acc[mt][nt][half * 2 + 0] + b0;
                v.y = acc[mt][nt][half * 2 + 1] + b1;
                if (dst == 0) {
                    *(float2*)&Yout[(size_t)m * Hh + nA] = v;
                } else {
                    const int bb   = m / Ss;
                    const int s    = m - bb * Ss;
                    const int head = nA >> 6;
                    const int d    = nA & 63;
                    float* dp = (dst == 1) ? g_q : (dst == 2) ? g_k : g_v;
                    *(float2*)&dp[(((size_t)(bb * NHh + head)) * Ss + s) * HDd + d] = v;
                }
            }
        }
    }
}

// ---------------------------------------------------------------------------
// Tensor-core causal flash attention (tf32 mma).
// grid: (S/64, B*NH), block 128 (4 warps).
// Each CTA: 64 q-rows; each warp: 16 q-rows. K/V tiles of 64 keys.
// Q fragments register-resident (pre-scaled by 1/8).
// Ks buffer holds K tile during S-phase, then reused for P.
// Vt holds V transposed: Vt[d][key].
// ---------------------------------------------------------------------------
__global__ __launch_bounds__(128)
void attn_tc()
{
    __shared__ uint32_t Ks[64][68];   // K tile (tf32); reused as P
    __shared__ uint32_t Vt[64][68];   // V^T tile (tf32)

    const int tid  = threadIdx.x;
    const int lane = tid & 31;
    const int wid  = tid >> 5;      // 0..3
    const int g    = lane >> 2;     // 0..7
    const int tg   = lane & 3;      // 0..3
    const int qb   = blockIdx.x;
    const int bh   = blockIdx.y;
    const int q0   = qb * 64;
    const int R0   = wid * 16;      // warp's q-row base within tile

    const float* Qg = g_q + (size_t)bh * Ss * HDd;
    const float* Kg = g_k + (size_t)bh * Ss * HDd;
    const float* Vg = g_v + (size_t)bh * Ss * HDd;

    // ---- stage Q (scaled by 1/8) into Ks, pull fragments to registers ----
    for (int u = tid; u < 64 * 16; u += 128) {
        const int r = u >> 4;
        const int c = (u & 15) << 2;
        float4 v = *(const float4*)&Qg[(size_t)(q0 + r) * 64 + c];
        Ks[r][c + 0] = f2tf32(v.x * 0.125f);
        Ks[r][c + 1] = f2tf32(v.y * 0.125f);
        Ks[r][c + 2] = f2tf32(v.z * 0.125f);
        Ks[r][c + 3] = f2tf32(v.w * 0.125f);
    }
    __syncthreads();

    uint32_t qf[8][4];
#pragma unroll
    for (int kc = 0; kc < 8; kc++) {
        qf[kc][0] = Ks[R0 + g][kc * 8 + tg];
        qf[kc][1] = Ks[R0 + g + 8][kc * 8 + tg];
        qf[kc][2] = Ks[R0 + g][kc * 8 + tg + 4];
        qf[kc][3] = Ks[R0 + g + 8][kc * 8 + tg + 4];
    }

    float oacc[8][4];
#pragma unroll
    for (int nt = 0; nt < 8; nt++)
#pragma unroll
        for (int r = 0; r < 4; r++) oacc[nt][r] = 0.f;
    float m0 = -1e30f, m1 = -1e30f, l0 = 0.f, l1 = 0.f;

    for (int kb = 0; kb <= qb; kb++) {
        const int k0 = kb * 64;
        __syncthreads();   // prev PV reads of Vt/Ps done; Q frag reads done (kb=0)

        // ---- load K tile -> Ks, V tile -> Vt (transposed) ----
        for (int u = tid; u < 64 * 16; u += 128) {
            const int r = u >> 4;
            const int c = (u & 15) << 2;
            float4 kv = *(const float4*)&Kg[(size_t)(k0 + r) * 64 + c];
            Ks[r][c + 0] = f2tf32(kv.x);
            Ks[r][c + 1] = f2tf32(kv.y);
            Ks[r][c + 2] = f2tf32(kv.z);
            Ks[r][c + 3] = f2tf32(kv.w);
            float4 vv = *(const float4*)&Vg[(size_t)(k0 + r) * 64 + c];
            Vt[c + 0][r] = f2tf32(vv.x);
            Vt[c + 1][r] = f2tf32(vv.y);
            Vt[c + 2][r] = f2tf32(vv.z);
            Vt[c + 3][r] = f2tf32(vv.w);
        }
        __syncthreads();

        // ---- S = Q K^T (scaled), 8 n-tiles of 8 cols ----
        float sacc[8][4];
#pragma unroll
        for (int nt = 0; nt < 8; nt++)
#pragma unroll
            for (int r = 0; r < 4; r++) sacc[nt][r] = 0.f;

#pragma unroll
        for (int kc = 0; kc < 8; kc++) {
#pragma unroll
            for (int nt = 0; nt < 8; nt++) {
                uint32_t kf[2];
                kf[0] = Ks[nt * 8 + g][kc * 8 + tg];
                kf[1] = Ks[nt * 8 + g][kc * 8 + tg + 4];
                mma_tf32(sacc[nt], qf[kc], kf, sacc[nt]);
            }
        }

        // ---- causal mask on diagonal tile ----
        if (kb == qb) {
            const int r0 = R0 + g;
            const int r1 = r0 + 8;
#pragma unroll
            for (int nt = 0; nt < 8; nt++) {
                const int c0 = nt * 8 + tg * 2;
                if (c0 > r0)     sacc[nt][0] = -1e30f;
                if (c0 + 1 > r0) sacc[nt][1] = -1e30f;
                if (c0 > r1)     sacc[nt][2] = -1e30f;
                if (c0 + 1 > r1) sacc[nt][3] = -1e30f;
            }
        }

        // ---- online softmax: row max ----
        float bm0 = -1e30f, bm1 = -1e30f;
#pragma unroll
        for (int nt = 0; nt < 8; nt++) {
            bm0 = fmaxf(bm0, fmaxf(sacc[nt][0], sacc[nt][1]));
            bm1 = fmaxf(bm1, fmaxf(sacc[nt][2], sacc[nt][3]));
        }
        bm0 = fmaxf(bm0, __shfl_xor_sync(0xffffffffu, bm0, 1));
        bm0 = fmaxf(bm0, __shfl_xor_sync(0xffffffffu, bm0, 2));
        bm1 = fmaxf(bm1, __shfl_xor_sync(0xffffffffu, bm1, 1));
        bm1 = fmaxf(bm1, __shfl_xor_sync(0xffffffffu, bm1, 2));

        const float nm0 = fmaxf(m0, bm0);
        const float nm1 = fmaxf(m1, bm1);
        const float c0f = __expf(m0 - nm0);
        const float c1f = __expf(m1 - nm1);
        m0 = nm0; m1 = nm1;
#pragma unroll
        for (int nt = 0; nt < 8; nt++) {
            oacc[nt][0] *= c0f; oacc[nt][1] *= c0f;
            oacc[nt][2] *= c1f; oacc[nt][3] *= c1f;
        }
        l0 *= c0f; l1 *= c1f;

        __syncthreads();   // all warps done reading Ks (K tile)

        // ---- P = exp(S - m): store to Ks (own warp stripe), accumulate sums ----
        float rs0 = 0.f, rs1 = 0.f;
#pragma unroll
        for (int nt = 0; nt < 8; nt++) {
            const int cc = nt * 8 + tg * 2;
            float p0 = __expf(sacc[nt][0] - nm0);
            float p1 = __expf(sacc[nt][1] - nm0);
            float p2 = __expf(sacc[nt][2] - nm1);
            float p3 = __expf(sacc[nt][3] - nm1);
            rs0 += p0 + p1;
            rs1 += p2 + p3;
            Ks[R0 + g][cc]         = f2tf32(p0);
            Ks[R0 + g][cc + 1]     = f2tf32(p1);
            Ks[R0 + g + 8][cc]     = f2tf32(p2);
            Ks[R0 + g + 8][cc + 1] = f2tf32(p3);
        }
        rs0 += __shfl_xor_sync(0xffffffffu, rs0, 1);
        rs0 += __shfl_xor_sync(0xffffffffu, rs0, 2);
        rs1 += __shfl_xor_sync(0xffffffffu, rs1, 1);
        rs1 += __shfl_xor_sync(0xffffffffu, rs1, 2);
        l0 += rs0; l1 += rs1;

        __syncwarp();      // P stripe visible within warp

        // ---- O += P @ V  (A = P rows of this warp, B = Vt) ----
#pragma unroll
        for (int kc = 0; kc < 8; kc++) {
            uint32_t af[4];
            af[0] = Ks[R0 + g][kc * 8 + tg];
            af[1] = Ks[R0 + g + 8][kc * 8 + tg];
            af[2] = Ks[R0 + g][kc * 8 + tg + 4];
            af[3] = Ks[R0 + g + 8][kc * 8 + tg + 4];
#pragma unroll
            for (int nt = 0; nt < 8; nt++) {
                uint32_t bf[2];
                bf[0] = Vt[nt * 8 + g][kc * 8 + tg];
                bf[1] = Vt[nt * 8 + g][kc * 8 + tg + 4];
                mma_tf32(oacc[nt], af, bf, oacc[nt]);
            }
        }
    }

    // ---- normalize + writeback: ctx[b, s, head*64 + d] ----
    const float inv0 = 1.f / l0;
    const float inv1 = 1.f / l1;
    const int b    = bh / NHh;
    const int head = bh - b * NHh;
    const int s0   = q0 + R0 + g;
    const int s1   = s0 + 8;
#pragma unroll
    for (int nt = 0; nt < 8; nt++) {
        const int col = head * 64 + nt * 8 + tg * 2;
        float2 v0, v1;
        v0.x = oacc[nt][0] * inv0; v0.y = oacc[nt][1] * inv0;
        v1.x = oacc[nt][2] * inv1; v1.y = oacc[nt][3] * inv1;
        *(float2*)&g_ctx[((size_t)(b * Ss) + s0) * Hh + col] = v0;
        *(float2*)&g_ctx[((size_t)(b * Ss) + s1) * Hh + col] = v1;
    }
}

// ---------------------------------------------------------------------------
// kernel_launch
// inputs: 0 hidden_states, 1 Wq, 2 bq, 3 Wk, 4 bk, 5 Wv, 6 bv, 7 Wo, 8 bo
// ---------------------------------------------------------------------------
extern "C" void kernel_launch(void* const* d_in, const int* in_sizes, int n_in,
                              void* d_out, int out_size)
{
    const float* x  = (const float*)d_in[0];
    const float* Wq = (const float*)d_in[1];
    const float* bq = (const float*)d_in[2];
    const float* Wk = (const float*)d_in[3];
    const float* bk = (const float*)d_in[4];
    const float* Wv = (const float*)d_in[5];
    const float* bv = (const float*)d_in[6];
    const float* Wo = (const float*)d_in[7];
    const float* bo = (const float*)d_in[8];
    float* out = (float*)d_out;

    dim3 ggrid(Hh / 128, Mrows / 128);   // (8, 32)
    gemm_tf32<<<ggrid, 256>>>(x, Wq, bq, nullptr, 0, 1);
    gemm_tf32<<<ggrid, 256>>>(x, Wk, bk, nullptr, 0, 2);
    gemm_tf32<<<ggrid, 256>>>(x, Wv, bv, nullptr, 0, 3);

    dim3 agrid(Ss / 64, Bb * NHh);       // (32, 32)
    attn_tc<<<agrid, 128>>>();

    gemm_tf32<<<ggrid, 256>>>(x, Wo, bo, out, 1, 0);
}

// round 5
// speedup vs baseline: 5.0250x; 1.1194x over previous
#include <cuda_runtime.h>
#include <cstdint>

// Problem constants
#define Bb   2
#define Ss   2048
#define Hh   1024
#define NHh  16
#define HDd  64
#define Mrows (Bb*Ss)   // 4096

// ---------------------------------------------------------------------------
// Device scratch (no allocations allowed)
// ---------------------------------------------------------------------------
__device__ float g_q[Bb*NHh*Ss*HDd];    // [b,h,s,d]
__device__ float g_k[Bb*NHh*Ss*HDd];
__device__ float g_v[Bb*NHh*Ss*HDd];
__device__ float g_ctx[Bb*Ss*Hh];       // [b,s,h]

__device__ __forceinline__ uint32_t f2tf32(float x) {
    uint32_t r;
    asm("cvt.rna.tf32.f32 %0, %1;" : "=r"(r) : "f"(x));
    return r;
}

__device__ __forceinline__ void mma_tf32(float d[4], const uint32_t a[4],
                                         const uint32_t b[2], const float c[4]) {
    asm volatile(
        "mma.sync.aligned.m16n8k8.row.col.f32.tf32.tf32.f32 "
        "{%0,%1,%2,%3}, {%4,%5,%6,%7}, {%8,%9}, {%10,%11,%12,%13};\n"
        : "=f"(d[0]), "=f"(d[1]), "=f"(d[2]), "=f"(d[3])
        : "r"(a[0]), "r"(a[1]), "r"(a[2]), "r"(a[3]),
          "r"(b[0]), "r"(b[1]),
          "f"(c[0]), "f"(c[1]), "f"(c[2]), "f"(c[3]));
}

// ---------------------------------------------------------------------------
// tf32 tensor-core GEMM body: Y[M,N] = X[M,K] @ W[N,K]^T + bias
// CTA tile 128x128, BK=32, 256 threads. dst: 0 -> Yout; 1/2/3 -> g_q/g_k/g_v
// ---------------------------------------------------------------------------
__device__ __forceinline__
void gemm_body(const float* __restrict__ X,
               const float* __restrict__ W,
               const float* __restrict__ bias,
               float* __restrict__ Yout,
               int dst, int bx, int by)
{
    __shared__ uint32_t A_s[128][36];
    __shared__ uint32_t B_s[128][36];

    const int tid  = threadIdx.x;
    const int lane = tid & 31;
    const int wid  = tid >> 5;
    const int wm   = (wid & 1) * 64;
    const int wn   = (wid >> 1) * 32;
    const int m0   = by * 128;
    const int n0   = bx * 128;

    const int g  = lane >> 2;
    const int tg = lane & 3;

    const int lrow = tid >> 1;
    const int lcol = (tid & 1) << 4;
    const float* ag = X + (size_t)(m0 + lrow) * Hh + lcol;
    const float* bg = W + (size_t)(n0 + lrow) * Hh + lcol;

    float acc[4][4][4];
#pragma unroll
    for (int mt = 0; mt < 4; mt++)
#pragma unroll
        for (int nt = 0; nt < 4; nt++)
#pragma unroll
            for (int r = 0; r < 4; r++) acc[mt][nt][r] = 0.f;

    float4 ra[4], rb[4];
#pragma unroll
    for (int j = 0; j < 4; j++) {
        ra[j] = *(const float4*)(ag + j * 4);
        rb[j] = *(const float4*)(bg + j * 4);
    }

    for (int k0 = 0; k0 < Hh; k0 += 32) {
#pragma unroll
        for (int j = 0; j < 4; j++) {
            uint4 ua, ub;
            ua.x = f2tf32(ra[j].x); ua.y = f2tf32(ra[j].y);
            ua.z = f2tf32(ra[j].z); ua.w = f2tf32(ra[j].w);
            ub.x = f2tf32(rb[j].x); ub.y = f2tf32(rb[j].y);
            ub.z = f2tf32(rb[j].z); ub.w = f2tf32(rb[j].w);
            *(uint4*)&A_s[lrow][lcol + j * 4] = ua;
            *(uint4*)&B_s[lrow][lcol + j * 4] = ub;
        }
        __syncthreads();

        if (k0 + 32 < Hh) {
            const float* agn = ag + k0 + 32;
            const float* bgn = bg + k0 + 32;
#pragma unroll
            for (int j = 0; j < 4; j++) {
                ra[j] = *(const float4*)(agn + j * 4);
                rb[j] = *(const float4*)(bgn + j * 4);
            }
        }

#pragma unroll
        for (int kc = 0; kc < 32; kc += 8) {
            uint32_t af[4][4];
            uint32_t bf[4][2];
#pragma unroll
            for (int mt = 0; mt < 4; mt++) {
                const int r = wm + mt * 16 + g;
                af[mt][0] = A_s[r][kc + tg];
                af[mt][1] = A_s[r + 8][kc + tg];
                af[mt][2] = A_s[r][kc + tg + 4];
                af[mt][3] = A_s[r + 8][kc + tg + 4];
            }
#pragma unroll
            for (int nt = 0; nt < 4; nt++) {
                const int cN = wn + nt * 8 + g;
                bf[nt][0] = B_s[cN][kc + tg];
                bf[nt][1] = B_s[cN][kc + tg + 4];
            }
#pragma unroll
            for (int mt = 0; mt < 4; mt++)
#pragma unroll
                for (int nt = 0; nt < 4; nt++)
                    mma_tf32(acc[mt][nt], af[mt], bf[nt], acc[mt][nt]);
        }
        __syncthreads();
    }

#pragma unroll
    for (int mt = 0; mt < 4; mt++) {
#pragma unroll
        for (int nt = 0; nt < 4; nt++) {
            const int mA = m0 + wm + mt * 16 + g;
            const int nA = n0 + wn + nt * 8 + tg * 2;
            const float b0 = bias[nA], b1 = bias[nA + 1];
#pragma unroll
            for (int half = 0; half < 2; half++) {
                const int m = mA + half * 8;
                float2 v;
                v.x = acc[mt][nt][half * 2 + 0] + b0;
                v.y = acc[mt][nt][half * 2 + 1] + b1;
                if (dst == 0) {
                    *(float2*)&Yout[(size_t)m * Hh + nA] = v;
                } else {
                    const int bb   = m / Ss;
                    const int s    = m - bb * Ss;
                    const int head = nA >> 6;
                    const int d    = nA & 63;
                    float* dp = (dst == 1) ? g_q : (dst == 2) ? g_k : g_v;
                    *(float2*)&dp[(((size_t)(bb * NHh + head)) * Ss + s) * HDd + d] = v;
                }
            }
        }
    }
}

// Fused QKV projection: blockIdx.z selects which projection.
__global__ __launch_bounds__(256)
void gemm_qkv(const float* __restrict__ x,
              const float* __restrict__ Wq, const float* __restrict__ bq,
              const float* __restrict__ Wk, const float* __restrict__ bk,
              const float* __restrict__ Wv, const float* __restrict__ bv)
{
    const int z = blockIdx.z;
    const float* W = (z == 0) ? Wq : (z == 1) ? Wk : Wv;
    const float* b = (z == 0) ? bq : (z == 1) ? bk : bv;
    gemm_body(x, W, b, nullptr, z + 1, blockIdx.x, blockIdx.y);
}

// Output projection: g_ctx @ Wo^T + bo -> out
__global__ __launch_bounds__(256)
void gemm_out(const float* __restrict__ Wo, const float* __restrict__ bo,
              float* __restrict__ out)
{
    gemm_body(g_ctx, Wo, bo, out, 0, blockIdx.x, blockIdx.y);
}

// ---------------------------------------------------------------------------
// Tensor-core causal flash attention (tf32 mma), v4.
// grid: (S/64, B*NH), block 128 (4 warps). Heavy q-tiles scheduled first.
// Each warp: 16 q-rows. K/V tiles of 64 keys.
// Ks holds K during S phase, then is reused for P (per-warp stripes).
// Vs holds V in natural [key][dim] layout (stride 72 -> conflict-free B frags).
// ---------------------------------------------------------------------------
__global__ __launch_bounds__(128)
void attn_tc()
{
    __shared__ uint32_t Ks[64][68];   // Q staging / K tile / P tile (tf32)
    __shared__ uint32_t Vs[64][72];   // V tile (tf32), natural layout

    const int tid  = threadIdx.x;
    const int lane = tid & 31;
    const int wid  = tid >> 5;      // 0..3
    const int g    = lane >> 2;     // 0..7
    const int tg   = lane & 3;      // 0..3
    const int qb   = gridDim.x - 1 - blockIdx.x;   // heavy tiles first
    const int bh   = blockIdx.y;
    const int q0   = qb * 64;
    const int R0   = wid * 16;      // warp's q-row base within tile

    const float* Qg = g_q + (size_t)bh * Ss * HDd;
    const float* Kg = g_k + (size_t)bh * Ss * HDd;
    const float* Vg = g_v + (size_t)bh * Ss * HDd;

    // ---- stage Q (scaled by 1/8) into Ks, pull fragments to registers ----
    for (int u = tid; u < 64 * 16; u += 128) {
        const int r = u >> 4;
        const int c = (u & 15) << 2;
        float4 v = *(const float4*)&Qg[(size_t)(q0 + r) * 64 + c];
        uint4 uq;
        uq.x = f2tf32(v.x * 0.125f);
        uq.y = f2tf32(v.y * 0.125f);
        uq.z = f2tf32(v.z * 0.125f);
        uq.w = f2tf32(v.w * 0.125f);
        *(uint4*)&Ks[r][c] = uq;
    }
    __syncthreads();

    uint32_t qf[8][4];
#pragma unroll
    for (int kc = 0; kc < 8; kc++) {
        qf[kc][0] = Ks[R0 + g][kc * 8 + tg];
        qf[kc][1] = Ks[R0 + g + 8][kc * 8 + tg];
        qf[kc][2] = Ks[R0 + g][kc * 8 + tg + 4];
        qf[kc][3] = Ks[R0 + g + 8][kc * 8 + tg + 4];
    }

    float oacc[8][4];
#pragma unroll
    for (int nt = 0; nt < 8; nt++)
#pragma unroll
        for (int r = 0; r < 4; r++) oacc[nt][r] = 0.f;
    float m0 = -1e30f, m1 = -1e30f, l0 = 0.f, l1 = 0.f;

    for (int kb = 0; kb <= qb; kb++) {
        const int k0 = kb * 64;
        __syncthreads();   // prev tile's P (Ks) and V (Vs) reads complete

        // ---- load K tile -> Ks, V tile -> Vs (both tf32, STS.128) ----
        for (int u = tid; u < 64 * 16; u += 128) {
            const int r = u >> 4;
            const int c = (u & 15) << 2;
            float4 kv = *(const float4*)&Kg[(size_t)(k0 + r) * 64 + c];
            uint4 uk;
            uk.x = f2tf32(kv.x); uk.y = f2tf32(kv.y);
            uk.z = f2tf32(kv.z); uk.w = f2tf32(kv.w);
            *(uint4*)&Ks[r][c] = uk;
            float4 vv = *(const float4*)&Vg[(size_t)(k0 + r) * 64 + c];
            uint4 uv;
            uv.x = f2tf32(vv.x); uv.y = f2tf32(vv.y);
            uv.z = f2tf32(vv.z); uv.w = f2tf32(vv.w);
            *(uint4*)&Vs[r][c] = uv;
        }
        __syncthreads();

        // ---- S = Q K^T (scaled) ----
        float sacc[8][4];
#pragma unroll
        for (int nt = 0; nt < 8; nt++)
#pragma unroll
            for (int r = 0; r < 4; r++) sacc[nt][r] = 0.f;

#pragma unroll
        for (int kc = 0; kc < 8; kc++) {
#pragma unroll
            for (int nt = 0; nt < 8; nt++) {
                uint32_t kf[2];
                kf[0] = Ks[nt * 8 + g][kc * 8 + tg];
                kf[1] = Ks[nt * 8 + g][kc * 8 + tg + 4];
                mma_tf32(sacc[nt], qf[kc], kf, sacc[nt]);
            }
        }

        // ---- causal mask on diagonal tile ----
        if (kb == qb) {
            const int r0 = R0 + g;
            const int r1 = r0 + 8;
#pragma unroll
            for (int nt = 0; nt < 8; nt++) {
                const int c0 = nt * 8 + tg * 2;
                if (c0 > r0)     sacc[nt][0] = -1e30f;
                if (c0 + 1 > r0) sacc[nt][1] = -1e30f;
                if (c0 > r1)     sacc[nt][2] = -1e30f;
                if (c0 + 1 > r1) sacc[nt][3] = -1e30f;
            }
        }

        // ---- online softmax: row max ----
        float bm0 = -1e30f, bm1 = -1e30f;
#pragma unroll
        for (int nt = 0; nt < 8; nt++) {
            bm0 = fmaxf(bm0, fmaxf(sacc[nt][0], sacc[nt][1]));
            bm1 = fmaxf(bm1, fmaxf(sacc[nt][2], sacc[nt][3]));
        }
        bm0 = fmaxf(bm0, __shfl_xor_sync(0xffffffffu, bm0, 1));
        bm0 = fmaxf(bm0, __shfl_xor_sync(0xffffffffu, bm0, 2));
        bm1 = fmaxf(bm1, __shfl_xor_sync(0xffffffffu, bm1, 1));
        bm1 = fmaxf(bm1, __shfl_xor_sync(0xffffffffu, bm1, 2));

        const float nm0 = fmaxf(m0, bm0);
        const float nm1 = fmaxf(m1, bm1);
        const float c0f = __expf(m0 - nm0);
        const float c1f = __expf(m1 - nm1);
        m0 = nm0; m1 = nm1;
#pragma unroll
        for (int nt = 0; nt < 8; nt++) {
            oacc[nt][0] *= c0f; oacc[nt][1] *= c0f;
            oacc[nt][2] *= c1f; oacc[nt][3] *= c1f;
        }
        l0 *= c0f; l1 *= c1f;

        __syncthreads();   // all warps done reading Ks (K tile)

        // ---- P = exp(S - m) -> Ks (own warp stripe) ----
        float rs0 = 0.f, rs1 = 0.f;
#pragma unroll
        for (int nt = 0; nt < 8; nt++) {
            const int cc = nt * 8 + tg * 2;
            float p0 = __expf(sacc[nt][0] - nm0);
            float p1 = __expf(sacc[nt][1] - nm0);
            float p2 = __expf(sacc[nt][2] - nm1);
            float p3 = __expf(sacc[nt][3] - nm1);
            rs0 += p0 + p1;
            rs1 += p2 + p3;
            Ks[R0 + g][cc]         = f2tf32(p0);
            Ks[R0 + g][cc + 1]     = f2tf32(p1);
            Ks[R0 + g + 8][cc]     = f2tf32(p2);
            Ks[R0 + g + 8][cc + 1] = f2tf32(p3);
        }
        rs0 += __shfl_xor_sync(0xffffffffu, rs0, 1);
        rs0 += __shfl_xor_sync(0xffffffffu, rs0, 2);
        rs1 += __shfl_xor_sync(0xffffffffu, rs1, 1);
        rs1 += __shfl_xor_sync(0xffffffffu, rs1, 2);
        l0 += rs0; l1 += rs1;

        __syncwarp();      // P stripe visible within warp

        // ---- O += P @ V  (A = P rows of this warp, B = natural-layout Vs) ----
#pragma unroll
        for (int kc = 0; kc < 8; kc++) {
            uint32_t af[4];
            af[0] = Ks[R0 + g][kc * 8 + tg];
            af[1] = Ks[R0 + g + 8][kc * 8 + tg];
            af[2] = Ks[R0 + g][kc * 8 + tg + 4];
            af[3] = Ks[R0 + g + 8][kc * 8 + tg + 4];
#pragma unroll
            for (int nt = 0; nt < 8; nt++) {
                uint32_t bf[2];
                bf[0] = Vs[kc * 8 + tg][nt * 8 + g];
                bf[1] = Vs[kc * 8 + tg + 4][nt * 8 + g];
                mma_tf32(oacc[nt], af, bf, oacc[nt]);
            }
        }
    }

    // ---- normalize + writeback: ctx[b, s, head*64 + d] ----
    const float inv0 = 1.f / l0;
    const float inv1 = 1.f / l1;
    const int b    = bh / NHh;
    const int head = bh - b * NHh;
    const int s0   = q0 + R0 + g;
    const int s1   = s0 + 8;
#pragma unroll
    for (int nt = 0; nt < 8; nt++) {
        const int col = head * 64 + nt * 8 + tg * 2;
        float2 v0, v1;
        v0.x = oacc[nt][0] * inv0; v0.y = oacc[nt][1] * inv0;
        v1.x = oacc[nt][2] * inv1; v1.y = oacc[nt][3] * inv1;
        *(float2*)&g_ctx[((size_t)(b * Ss) + s0) * Hh + col] = v0;
        *(float2*)&g_ctx[((size_t)(b * Ss) + s1) * Hh + col] = v1;
    }
}

// ---------------------------------------------------------------------------
// kernel_launch
// inputs: 0 hidden_states, 1 Wq, 2 bq, 3 Wk, 4 bk, 5 Wv, 6 bv, 7 Wo, 8 bo
// ---------------------------------------------------------------------------
extern "C" void kernel_launch(void* const* d_in, const int* in_sizes, int n_in,
                              void* d_out, int out_size)
{
    const float* x  = (const float*)d_in[0];
    const float* Wq = (const float*)d_in[1];
    const float* bq = (const float*)d_in[2];
    const float* Wk = (const float*)d_in[3];
    const float* bk = (const float*)d_in[4];
    const float* Wv = (const float*)d_in[5];
    const float* bv = (const float*)d_in[6];
    const float* Wo = (const float*)d_in[7];
    const float* bo = (const float*)d_in[8];
    float* out = (float*)d_out;

    dim3 qkvgrid(Hh / 128, Mrows / 128, 3);   // (8, 32, 3)
    gemm_qkv<<<qkvgrid, 256>>>(x, Wq, bq, Wk, bk, Wv, bv);

    dim3 agrid(Ss / 64, Bb * NHh);            // (32, 32)
    attn_tc<<<agrid, 128>>>();

    dim3 ogrid(Hh / 128, Mrows / 128);        // (8, 32)
    gemm_out<<<ogrid, 256>>>(Wo, bo, out);
}

// round 6
// speedup vs baseline: 6.4635x; 1.2863x over previous
#include <cuda_runtime.h>
#include <cstdint>

// Problem constants
#define Bb   2
#define Ss   2048
#define Hh   1024
#define NHh  16
#define HDd  64
#define Mrows (Bb*Ss)   // 4096

// ---------------------------------------------------------------------------
// Device scratch (no allocations allowed). All tf32 payloads stored as u32 bits.
// ---------------------------------------------------------------------------
__device__ uint32_t g_xt[Mrows*Hh];        // X in tf32
__device__ uint32_t g_wt[4*Hh*Hh];         // Wq,Wk,Wv,Wo in tf32
__device__ uint32_t g_qt[Bb*NHh*Ss*HDd];   // Q (pre-scaled by 1/8), tf32, [b,h,s,d]
__device__ uint32_t g_kt[Bb*NHh*Ss*HDd];   // K tf32
__device__ uint32_t g_vt[Bb*NHh*Ss*HDd];   // V tf32
__device__ uint32_t g_ctxt[Bb*Ss*Hh];      // attention output, tf32, [b,s,h]

__device__ __forceinline__ uint32_t f2tf32(float x) {
    uint32_t r;
    asm("cvt.rna.tf32.f32 %0, %1;" : "=r"(r) : "f"(x));
    return r;
}

__device__ __forceinline__ void mma_tf32(float d[4], const uint32_t a[4],
                                         const uint32_t b[2], const float c[4]) {
    asm volatile(
        "mma.sync.aligned.m16n8k8.row.col.f32.tf32.tf32.f32 "
        "{%0,%1,%2,%3}, {%4,%5,%6,%7}, {%8,%9}, {%10,%11,%12,%13};\n"
        : "=f"(d[0]), "=f"(d[1]), "=f"(d[2]), "=f"(d[3])
        : "r"(a[0]), "r"(a[1]), "r"(a[2]), "r"(a[3]),
          "r"(b[0]), "r"(b[1]),
          "f"(c[0]), "f"(c[1]), "f"(c[2]), "f"(c[3]));
}

__device__ __forceinline__ void cp_async16(uint32_t smem_addr, const void* gptr) {
    asm volatile("cp.async.cg.shared.global [%0], [%1], 16;\n"
                 :: "r"(smem_addr), "l"(gptr));
}
__device__ __forceinline__ uint32_t s2u(const void* p) {
    return (uint32_t)__cvta_generic_to_shared(p);
}

// ---------------------------------------------------------------------------
// Prologue: convert X and the 4 weight matrices to tf32 once.
// grid 4096 x 256: i indexes float4 chunks.
// ---------------------------------------------------------------------------
__global__ __launch_bounds__(256)
void preconv(const float* __restrict__ x,
             const float* __restrict__ wq, const float* __restrict__ wk,
             const float* __restrict__ wv, const float* __restrict__ wo)
{
    const int i = blockIdx.x * blockDim.x + threadIdx.x;
    const int NX4 = (Mrows * Hh) / 4;   // 1,048,576
    const int NW4 = (Hh * Hh) / 4;      // 262,144

    if (i < NX4) {
        float4 v = ((const float4*)x)[i];
        uint4 u;
        u.x = f2tf32(v.x); u.y = f2tf32(v.y);
        u.z = f2tf32(v.z); u.w = f2tf32(v.w);
        ((uint4*)g_xt)[i] = u;
    }
    if (i < NW4) {
        const float* ws[4] = {wq, wk, wv, wo};
#pragma unroll
        for (int z = 0; z < 4; z++) {
            float4 v = ((const float4*)ws[z])[i];
            uint4 u;
            u.x = f2tf32(v.x); u.y = f2tf32(v.y);
            u.z = f2tf32(v.z); u.w = f2tf32(v.w);
            ((uint4*)(g_wt + (size_t)z * Hh * Hh))[i] = u;
        }
    }
}

// ---------------------------------------------------------------------------
// tf32 GEMM with cp.async 2-stage pipeline.
// CTA 128x128, BK=32, 128 threads = 4 warps (2m x 2n), warp tile 64x64.
// Inputs already tf32 (u32 bits). dst: 0 -> Yout fp32; 1/2/3 -> g_qt/kt/vt.
// Dynamic SMEM: 2 stages x (A 128x36 + B 128x36) u32 = 73728 bytes.
// ---------------------------------------------------------------------------
#define GEMM_STG   (2*128*36)                 // words per stage (A+B)
#define GEMM_SMEM  (2*GEMM_STG*4)             // bytes

__device__ __forceinline__
void gemm_load_stage(const uint32_t* __restrict__ A, const uint32_t* __restrict__ Bm,
                     uint32_t* dstA, int m0, int n0, int k0, int tid)
{
    uint32_t* dstB = dstA + 128*36;
#pragma unroll
    for (int j = 0; j < 8; j++) {
        const int id  = j * 128 + tid;     // 0..1023
        const int row = id >> 3;
        const int col = (id & 7) * 4;
        cp_async16(s2u(dstA + row*36 + col), A  + (size_t)(m0+row)*Hh + k0 + col);
        cp_async16(s2u(dstB + row*36 + col), Bm + (size_t)(n0+row)*Hh + k0 + col);
    }
}

__device__ __forceinline__
void gemm_tc_body(const uint32_t* __restrict__ A, const uint32_t* __restrict__ Bm,
                  const float* __restrict__ bias, float* __restrict__ Yout,
                  int dst, int bx, int by, uint32_t* smem)
{
    const int tid  = threadIdx.x;
    const int lane = tid & 31;
    const int wid  = tid >> 5;
    const int wm   = (wid & 1) * 64;
    const int wn   = (wid >> 1) * 64;
    const int m0   = by * 128;
    const int n0   = bx * 128;
    const int g    = lane >> 2;
    const int tg   = lane & 3;

    float acc[4][8][4];
#pragma unroll
    for (int mt = 0; mt < 4; mt++)
#pragma unroll
        for (int nt = 0; nt < 8; nt++)
#pragma unroll
            for (int r = 0; r < 4; r++) acc[mt][nt][r] = 0.f;

    gemm_load_stage(A, Bm, smem, m0, n0, 0, tid);
    asm volatile("cp.async.commit_group;\n");

    for (int kt = 0; kt < 32; kt++) {
        if (kt + 1 < 32) {
            gemm_load_stage(A, Bm, smem + ((kt+1)&1)*GEMM_STG, m0, n0, (kt+1)*32, tid);
            asm volatile("cp.async.commit_group;\n");
            asm volatile("cp.async.wait_group 1;\n");
        } else {
            asm volatile("cp.async.wait_group 0;\n");
        }
        __syncthreads();

        const uint32_t* As = smem + (kt & 1) * GEMM_STG;
        const uint32_t* Bs = As + 128*36;

#pragma unroll
        for (int kc = 0; kc < 32; kc += 8) {
            uint32_t af[4][4];
            uint32_t bf[8][2];
#pragma unroll
            for (int mt = 0; mt < 4; mt++) {
                const uint32_t* r0p = As + (wm + mt*16 + g)*36 + kc;
                af[mt][0] = r0p[tg];
                af[mt][2] = r0p[tg + 4];
                const uint32_t* r1p = r0p + 8*36;
                af[mt][1] = r1p[tg];
                af[mt][3] = r1p[tg + 4];
            }
#pragma unroll
            for (int nt = 0; nt < 8; nt++) {
                const uint32_t* cp_ = Bs + (wn + nt*8 + g)*36 + kc;
                bf[nt][0] = cp_[tg];
                bf[nt][1] = cp_[tg + 4];
            }
#pragma unroll
            for (int mt = 0; mt < 4; mt++)
#pragma unroll
                for (int nt = 0; nt < 8; nt++)
                    mma_tf32(acc[mt][nt], af[mt], bf[nt], acc[mt][nt]);
        }
        __syncthreads();
    }

    // epilogue
    const float qscale = (dst == 1) ? 0.125f : 1.0f;
#pragma unroll
    for (int mt = 0; mt < 4; mt++) {
#pragma unroll
        for (int nt = 0; nt < 8; nt++) {
            const int mA = m0 + wm + mt*16 + g;
            const int nA = n0 + wn + nt*8 + tg*2;
            const float b0 = bias[nA], b1 = bias[nA + 1];
#pragma unroll
            for (int half = 0; half < 2; half++) {
                const int m = mA + half * 8;
                float vx = acc[mt][nt][half*2 + 0] + b0;
                float vy = acc[mt][nt][half*2 + 1] + b1;
                if (dst == 0) {
                    float2 v; v.x = vx; v.y = vy;
                    *(float2*)&Yout[(size_t)m * Hh + nA] = v;
                } else {
                    const int bb   = m / Ss;
                    const int s    = m - bb * Ss;
                    const int head = nA >> 6;
                    const int d    = nA & 63;
                    uint32_t* dp = (dst == 1) ? g_qt : (dst == 2) ? g_kt : g_vt;
                    uint2 u;
                    u.x = f2tf32(vx * qscale);
                    u.y = f2tf32(vy * qscale);
                    *(uint2*)&dp[(((size_t)(bb * NHh + head)) * Ss + s) * HDd + d] = u;
                }
            }
        }
    }
}

__global__ __launch_bounds__(128)
void gemm_qkv(const float* __restrict__ bq, const float* __restrict__ bk,
              const float* __restrict__ bv)
{
    extern __shared__ uint32_t smem_g[];
    const int z = blockIdx.z;
    const float* bias = (z == 0) ? bq : (z == 1) ? bk : bv;
    gemm_tc_body(g_xt, g_wt + (size_t)z * Hh * Hh, bias, nullptr,
                 z + 1, blockIdx.x, blockIdx.y, smem_g);
}

__global__ __launch_bounds__(128)
void gemm_out(const float* __restrict__ bo, float* __restrict__ out)
{
    extern __shared__ uint32_t smem_g[];
    gemm_tc_body(g_ctxt, g_wt + (size_t)3 * Hh * Hh, bo, out,
                 0, blockIdx.x, blockIdx.y, smem_g);
}

// ---------------------------------------------------------------------------
// Tensor-core causal flash attention (tf32 mma), v5.
// grid: (S/64, B*NH), block 128 (4 warps). Heavy q-tiles first.
// Inputs (g_qt/kt/vt) already tf32; Q pre-scaled. No cvt in hot loop.
// Separate P buffer -> 2 syncthreads per k-tile.
// Dynamic SMEM: Ks 64x68 + Vs 64x72 + Ps 64x68 = 53248 bytes.
// ---------------------------------------------------------------------------
#define ATTN_SMEM ((64*68 + 64*72 + 64*68)*4)

__global__ __launch_bounds__(128)
void attn_tc()
{
    extern __shared__ uint32_t asmem[];
    uint32_t (*Ks)[68] = (uint32_t(*)[68])asmem;                    // Q staging / K tile
    uint32_t (*Vs)[72] = (uint32_t(*)[72])(asmem + 64*68);          // V tile
    uint32_t (*Ps)[68] = (uint32_t(*)[68])(asmem + 64*68 + 64*72);  // P tile

    const int tid  = threadIdx.x;
    const int lane = tid & 31;
    const int wid  = tid >> 5;      // 0..3
    const int g    = lane >> 2;     // 0..7
    const int tg   = lane & 3;      // 0..3
    const int qb   = gridDim.x - 1 - blockIdx.x;   // heavy tiles first
    const int bh   = blockIdx.y;
    const int q0   = qb * 64;
    const int R0   = wid * 16;      // warp's q-row base within tile

    const uint32_t* Qg = g_qt + (size_t)bh * Ss * HDd;
    const uint32_t* Kg = g_kt + (size_t)bh * Ss * HDd;
    const uint32_t* Vg = g_vt + (size_t)bh * Ss * HDd;

    // ---- stage Q into Ks (already tf32 + pre-scaled), pull fragments ----
    for (int u = tid; u < 64 * 16; u += 128) {
        const int r = u >> 4;
        const int c = (u & 15) << 2;
        *(uint4*)&Ks[r][c] = *(const uint4*)&Qg[(size_t)(q0 + r) * 64 + c];
    }
    __syncthreads();

    uint32_t qf[8][4];
#pragma unroll
    for (int kc = 0; kc < 8; kc++) {
        qf[kc][0] = Ks[R0 + g][kc * 8 + tg];
        qf[kc][1] = Ks[R0 + g + 8][kc * 8 + tg];
        qf[kc][2] = Ks[R0 + g][kc * 8 + tg + 4];
        qf[kc][3] = Ks[R0 + g + 8][kc * 8 + tg + 4];
    }

    float oacc[8][4];
#pragma unroll
    for (int nt = 0; nt < 8; nt++)
#pragma unroll
        for (int r = 0; r < 4; r++) oacc[nt][r] = 0.f;
    float m0 = -1e30f, m1 = -1e30f, l0 = 0.f, l1 = 0.f;

    for (int kb = 0; kb <= qb; kb++) {
        const int k0 = kb * 64;
        __syncthreads();   // prev tile's Ks/Vs/Ps reads complete (and Q frags, kb=0)

        // ---- load K tile -> Ks, V tile -> Vs (pure uint4 copies) ----
        for (int u = tid; u < 64 * 16; u += 128) {
            const int r = u >> 4;
            const int c = (u & 15) << 2;
            *(uint4*)&Ks[r][c] = *(const uint4*)&Kg[(size_t)(k0 + r) * 64 + c];
            *(uint4*)&Vs[r][c] = *(const uint4*)&Vg[(size_t)(k0 + r) * 64 + c];
        }
        __syncthreads();

        // ---- S = Q K^T (Q pre-scaled) ----
        float sacc[8][4];
#pragma unroll
        for (int nt = 0; nt < 8; nt++)
#pragma unroll
            for (int r = 0; r < 4; r++) sacc[nt][r] = 0.f;

#pragma unroll
        for (int kc = 0; kc < 8; kc++) {
#pragma unroll
            for (int nt = 0; nt < 8; nt++) {
                uint32_t kf[2];
                kf[0] = Ks[nt * 8 + g][kc * 8 + tg];
                kf[1] = Ks[nt * 8 + g][kc * 8 + tg + 4];
                mma_tf32(sacc[nt], qf[kc], kf, sacc[nt]);
            }
        }

        // ---- causal mask on diagonal tile ----
        if (kb == qb) {
            const int r0 = R0 + g;
            const int r1 = r0 + 8;
#pragma unroll
            for (int nt = 0; nt < 8; nt++) {
                const int c0 = nt * 8 + tg * 2;
                if (c0 > r0)     sacc[nt][0] = -1e30f;
                if (c0 + 1 > r0) sacc[nt][1] = -1e30f;
                if (c0 > r1)     sacc[nt][2] = -1e30f;
                if (c0 + 1 > r1) sacc[nt][3] = -1e30f;
            }
        }

        // ---- online softmax: row max ----
        float bm0 = -1e30f, bm1 = -1e30f;
#pragma unroll
        for (int nt = 0; nt < 8; nt++) {
            bm0 = fmaxf(bm0, fmaxf(sacc[nt][0], sacc[nt][1]));
            bm1 = fmaxf(bm1, fmaxf(sacc[nt][2], sacc[nt][3]));
        }
        bm0 = fmaxf(bm0, __shfl_xor_sync(0xffffffffu, bm0, 1));
        bm0 = fmaxf(bm0, __shfl_xor_sync(0xffffffffu, bm0, 2));
        bm1 = fmaxf(bm1, __shfl_xor_sync(0xffffffffu, bm1, 1));
        bm1 = fmaxf(bm1, __shfl_xor_sync(0xffffffffu, bm1, 2));

        const float nm0 = fmaxf(m0, bm0);
        const float nm1 = fmaxf(m1, bm1);
        const float c0f = __expf(m0 - nm0);
        const float c1f = __expf(m1 - nm1);
        m0 = nm0; m1 = nm1;
#pragma unroll
        for (int nt = 0; nt < 8; nt++) {
            oacc[nt][0] *= c0f; oacc[nt][1] *= c0f;
            oacc[nt][2] *= c1f; oacc[nt][3] *= c1f;
        }
        l0 *= c0f; l1 *= c1f;

        // ---- P = exp(S - m) -> Ps (own warp stripe; no cross-warp use) ----
        float rs0 = 0.f, rs1 = 0.f;
#pragma unroll
        for (int nt = 0; nt < 8; nt++) {
            const int cc = nt * 8 + tg * 2;
            float p0 = __expf(sacc[nt][0] - nm0);
            float p1 = __expf(sacc[nt][1] - nm0);
            float p2 = __expf(sacc[nt][2] - nm1);
            float p3 = __expf(sacc[nt][3] - nm1);
            rs0 += p0 + p1;
            rs1 += p2 + p3;
            Ps[R0 + g][cc]         = f2tf32(p0);
            Ps[R0 + g][cc + 1]     = f2tf32(p1);
            Ps[R0 + g + 8][cc]     = f2tf32(p2);
            Ps[R0 + g + 8][cc + 1] = f2tf32(p3);
        }
        rs0 += __shfl_xor_sync(0xffffffffu, rs0, 1);
        rs0 += __shfl_xor_sync(0xffffffffu, rs0, 2);
        rs1 += __shfl_xor_sync(0xffffffffu, rs1, 1);
        rs1 += __shfl_xor_sync(0xffffffffu, rs1, 2);
        l0 += rs0; l1 += rs1;

        __syncwarp();      // P stripe visible within warp

        // ---- O += P @ V ----
#pragma unroll
        for (int kc = 0; kc < 8; kc++) {
            uint32_t af[4];
            af[0] = Ps[R0 + g][kc * 8 + tg];
            af[1] = Ps[R0 + g + 8][kc * 8 + tg];
            af[2] = Ps[R0 + g][kc * 8 + tg + 4];
            af[3] = Ps[R0 + g + 8][kc * 8 + tg + 4];
#pragma unroll
            for (int nt = 0; nt < 8; nt++) {
                uint32_t bf[2];
                bf[0] = Vs[kc * 8 + tg][nt * 8 + g];
                bf[1] = Vs[kc * 8 + tg + 4][nt * 8 + g];
                mma_tf32(oacc[nt], af, bf, oacc[nt]);
            }
        }
    }

    // ---- normalize + writeback ctx (tf32) ----
    const float inv0 = 1.f / l0;
    const float inv1 = 1.f / l1;
    const int b    = bh / NHh;
    const int head = bh - b * NHh;
    const int s0   = q0 + R0 + g;
    const int s1   = s0 + 8;
#pragma unroll
    for (int nt = 0; nt < 8; nt++) {
        const int col = head * 64 + nt * 8 + tg * 2;
        uint2 v0, v1;
        v0.x = f2tf32(oacc[nt][0] * inv0); v0.y = f2tf32(oacc[nt][1] * inv0);
        v1.x = f2tf32(oacc[nt][2] * inv1); v1.y = f2tf32(oacc[nt][3] * inv1);
        *(uint2*)&g_ctxt[((size_t)(b * Ss) + s0) * Hh + col] = v0;
        *(uint2*)&g_ctxt[((size_t)(b * Ss) + s1) * Hh + col] = v1;
    }
}

// ---------------------------------------------------------------------------
// kernel_launch
// inputs: 0 hidden_states, 1 Wq, 2 bq, 3 Wk, 4 bk, 5 Wv, 6 bv, 7 Wo, 8 bo
// ---------------------------------------------------------------------------
extern "C" void kernel_launch(void* const* d_in, const int* in_sizes, int n_in,
                              void* d_out, int out_size)
{
    const float* x  = (const float*)d_in[0];
    const float* Wq = (const float*)d_in[1];
    const float* bq = (const float*)d_in[2];
    const float* Wk = (const float*)d_in[3];
    const float* bk = (const float*)d_in[4];
    const float* Wv = (const float*)d_in[5];
    const float* bv = (const float*)d_in[6];
    const float* Wo = (const float*)d_in[7];
    const float* bo = (const float*)d_in[8];
    float* out = (float*)d_out;

    cudaFuncSetAttribute(gemm_qkv, cudaFuncAttributeMaxDynamicSharedMemorySize, GEMM_SMEM);
    cudaFuncSetAttribute(gemm_out, cudaFuncAttributeMaxDynamicSharedMemorySize, GEMM_SMEM);
    cudaFuncSetAttribute(attn_tc,  cudaFuncAttributeMaxDynamicSharedMemorySize, ATTN_SMEM);

    preconv<<<4096, 256>>>(x, Wq, Wk, Wv, Wo);

    dim3 qkvgrid(Hh / 128, Mrows / 128, 3);   // (8, 32, 3)
    gemm_qkv<<<qkvgrid, 128, GEMM_SMEM>>>(bq, bk, bv);

    dim3 agrid(Ss / 64, Bb * NHh);            // (32, 32)
    attn_tc<<<agrid, 128, ATTN_SMEM>>>();

    dim3 ogrid(Hh / 128, Mrows / 128);        // (8, 32)
    gemm_out<<<ogrid, 128, GEMM_SMEM>>>(bo, out);
}